// round 10
// baseline (speedup 1.0000x reference)
#include <cuda_runtime.h>
#include <cuda_bf16.h>

#define TPB  128
#define SLAB 128

__device__ double g_acc = 0.0;
__device__ unsigned int g_done = 0;

struct LayerParams {
    const float* pred;
    const float* ytr;
    int nblocks;
    int ncells;
    float s_aw[3], s_ah[3], i_aw[3], i_ah[3];
};

struct KParams {
    LayerParams L[3];
    const float* target;
    float* out;
    int totalBlocks;
};

// All 85 y_true values per cell stored as bf16 at smH[cell*86 + 1 + ch].
// Row stride 86 halves = 43 words (gcd(43,32)=1 -> conflict-free);
// +1 offset makes class pairs (ch=5+2m,6+2m) start at even half -> aligned bf16x2.
__shared__ __nv_bfloat16 smH[SLAB * 86];
__shared__ float         ws[4];

template<int G>
__device__ __forceinline__ float cell_loss(const float* __restrict__ pred,
                                           const float* __restrict__ target,
                                           int idx, const LayerParams& L)
{
    constexpr int cs = G * G;
    constexpr float invG = 1.f / (float)G;
    const int x = idx % G;
    const int y = (idx / G) % G;
    const int a = (idx / cs) % 3;
    const int b = idx / (3 * cs);

    // 32-bit offsets throughout (max ~22M elements, fits int): avoids 64-bit
    // address arithmetic (register pairs + double IMAD).
    const int pbase = ((b * 255 + a * 85) * G + y) * G + x;
    const float* __restrict__ p = pred + pbase;
    const __nv_bfloat16* tR = smH + threadIdx.x * 86 + 1;

    const float s_aw = L.s_aw[a], s_ah = L.s_ah[a];
    const float i_aw = L.i_aw[a], i_ah = L.i_ah[a];

    const float r0 = p[0];
    const float r1 = p[cs];
    const float r2 = p[2 * cs];
    const float r3 = p[3 * cs];
    const float r4 = p[4 * cs];
    const float t0 = __bfloat162float(tR[0]);
    const float t1 = __bfloat162float(tR[1]);
    const float t2 = __bfloat162float(tR[2]);
    const float t3 = __bfloat162float(tR[3]);
    const float om = __bfloat162float(tR[4]);

    const float gx = (float)x, gy = (float)y;
    float loss = 0.f;

    // bce(sigmoid(r), t) = softplus(-r) + (1-t)*r
    const float e0 = __expf(-r0), e1 = __expf(-r1), e4 = __expf(-r4);
    const float sp0 = __logf(1.f + e0);
    const float sp1 = __logf(1.f + e1);
    const float sp4 = __logf(1.f + e4);

    // ---- xy loss ---- (ref: true_xy = y_true[...,0:2]*[h,w] - grid_xy)
    const float truex = t0 * (float)G - gx;
    const float truey = t1 * (float)G - gy;
    const float bce_x = sp0 + (1.f - truex) * r0;
    const float bce_y = sp1 + (1.f - truey) * r1;
    const float ls = 2.f - t2 * t3;
    loss += om * ls * (bce_x + bce_y);

    // ---- wh loss ----
    float twh = __logf(t2 * i_aw);
    float thh = __logf(t3 * i_ah);
    if (!(om > 0.f)) { twh = 0.f; thh = 0.f; }
    const float dw = r2 - twh, dh = r3 - thh;
    loss += om * ls * 0.5f * (dw * dw + dh * dh);

    // ---- predicted box for IoU ----
    const float sx = __fdividef(1.f, 1.f + e0);
    const float sy = __fdividef(1.f, 1.f + e1);
    const float bx = (sx + gx) * invG;
    const float by = (sy + gy) * invG;
    const float bw = __expf(r2) * s_aw;
    const float bh = __expf(r3) * s_ah;
    const float b1minx = bx - 0.5f * bw, b1maxx = bx + 0.5f * bw;
    const float b1miny = by - 0.5f * bh, b1maxy = by + 0.5f * bh;
    const float a1 = bw * bh;

    // best_iou < 0.5 <=> for all n: 3*inter < a1 + a2   (division-free; L1-broadcast)
    bool neg = true;
    const float* __restrict__ tg = target + b * 100;
    #pragma unroll 4
    for (int n = 0; n < 20; n++) {
        const float tx = tg[n * 5 + 0];
        const float ty = tg[n * 5 + 1];
        const float tw = tg[n * 5 + 2];
        const float th = tg[n * 5 + 3];
        const float hw = 0.5f * tw, hh = 0.5f * th;
        float iw = fminf(b1maxx, tx + hw) - fmaxf(b1minx, tx - hw);
        float ih = fminf(b1maxy, ty + hh) - fmaxf(b1miny, ty - hh);
        iw = fmaxf(iw, 0.f);
        ih = fmaxf(ih, 0.f);
        const float inter = iw * ih;
        neg = neg && (3.f * inter < fmaf(tw, th, a1));
    }
    const float negf = neg ? 1.f : 0.f;

    // ---- conf loss ----
    const float conf_bce = sp4 + (1.f - om) * r4;
    loss += (om + (1.f - om) * negf) * conf_bce;

    // ---- class loss: 8 groups of 10; dual exp-product chains; fp32 lin ----
    float cls = 0.f;
    #pragma unroll
    for (int g = 0; g < 8; g++) {
        float r[10];
        #pragma unroll
        for (int j = 0; j < 10; j++) r[j] = p[(5 + g * 10 + j) * cs];

        float pa = 1.f, pb = 1.f;
        float lin = 0.f;
        #pragma unroll
        for (int j = 0; j < 10; j += 2) {
            pa = fmaf(pa, __expf(-r[j]),     pa);
            pb = fmaf(pb, __expf(-r[j + 1]), pb);
            const __nv_bfloat162 tp =
                *reinterpret_cast<const __nv_bfloat162*>(tR + 5 + g * 10 + j);
            lin = fmaf(1.f - __low2float(tp),  r[j],     lin);
            lin = fmaf(1.f - __high2float(tp), r[j + 1], lin);
        }
        cls += __logf(pa) + __logf(pb) + lin;
    }
    loss += om * cls;
    return loss;
}

__global__ __launch_bounds__(TPB, 9)
void yolo_fused_kernel(KParams kp)
{
    int lb = blockIdx.x;
    int layer = 0;
    if (lb >= kp.L[0].nblocks) {
        lb -= kp.L[0].nblocks; layer = 1;
        if (lb >= kp.L[1].nblocks) { lb -= kp.L[1].nblocks; layer = 2; }
    }
    const LayerParams& L = kp.L[layer];
    const int cellBase = lb * SLAB;
    const int ncells = min(SLAB, L.ncells - cellBase);   // multiple of 32

    const int lane = threadIdx.x & 31;
    const int wid  = threadIdx.x >> 5;

    // ---- per-warp staging: 8 groups of 4 cells (= exactly 85 float4s each).
    //      All index math hoisted: per-slot offsets are group-invariant. ----
    {
        const int wCellBase = wid * 32;
        if (wCellBase < ncells) {
            const float* __restrict__ src = L.ytr + (size_t)(cellBase + wCellBase) * 85;
            const float4* __restrict__ s4 = (const float4*)src;

            // precompute (valid, half-offsets) for the 3 float4 slots of this lane
            int off[3][4];
            bool val[3];
            #pragma unroll
            for (int m = 0; m < 3; m++) {
                const int j = lane + 32 * m;          // float4 index within group
                val[m] = (j < 85);
                const int lf = 4 * j;                 // float index within group (4 cells)
                const int c  = lf / 85;               // cell-in-group
                const int ch = lf - 85 * c;           // channel
                #pragma unroll
                for (int k = 0; k < 4; k++) {
                    const int cch = ch + k;
                    const int cr  = (cch >= 85) ? 1 : 0;
                    off[m][k] = (c + cr) * 86 + 1 + (cch - 85 * cr);
                }
            }

            #pragma unroll
            for (int g = 0; g < 8; g++) {
                const float4* __restrict__ gs = s4 + 85 * g;
                __nv_bfloat16* dst = smH + (wCellBase + 4 * g) * 86;
                #pragma unroll
                for (int m = 0; m < 3; m++) {
                    if (val[m]) {
                        const float4 v = gs[lane + 32 * m];
                        dst[off[m][0]] = __float2bfloat16_rn(v.x);
                        dst[off[m][1]] = __float2bfloat16_rn(v.y);
                        dst[off[m][2]] = __float2bfloat16_rn(v.z);
                        dst[off[m][3]] = __float2bfloat16_rn(v.w);
                    }
                }
            }
        }
        __syncwarp();
    }

    float loss = 0.f;
    if (threadIdx.x < ncells) {
        const int idx = cellBase + threadIdx.x;
        if (layer == 0)      loss = cell_loss<13>(L.pred, kp.target, idx, L);
        else if (layer == 1) loss = cell_loss<26>(L.pred, kp.target, idx, L);
        else                 loss = cell_loss<52>(L.pred, kp.target, idx, L);
    }

    // ---- block reduction ----
    const unsigned m = 0xFFFFFFFFu;
    #pragma unroll
    for (int o = 16; o > 0; o >>= 1) loss += __shfl_down_sync(m, loss, o);
    if (lane == 0) ws[wid] = loss;
    __syncthreads();
    if (threadIdx.x == 0) {
        const float bs = ws[0] + ws[1] + ws[2] + ws[3];
        atomicAdd(&g_acc, (double)bs);
        __threadfence();
        const unsigned done = atomicAdd(&g_done, 1u);
        if (done == (unsigned)(kp.totalBlocks - 1)) {
            __threadfence();
            kp.out[0] = (float)g_acc;
            g_acc = 0.0;       // reset for next graph replay
            g_done = 0;
        }
    }
}

static void fill_anchors(LayerParams& L, const float* aw, const float* ah)
{
    for (int a = 0; a < 3; a++) {
        L.s_aw[a] = aw[a] / 416.f;
        L.s_ah[a] = ah[a] / 416.f;
        L.i_aw[a] = 416.f / aw[a];
        L.i_ah[a] = 416.f / ah[a];
    }
}

extern "C" void kernel_launch(void* const* d_in, const int* in_sizes, int n_in,
                              void* d_out, int out_size)
{
    const float *p0, *p1, *p2, *t0, *t1, *t2;
    if (in_sizes[1] == in_sizes[0]) {
        // interleaved: y_pred0, y_true0, y_pred1, y_true1, y_pred2, y_true2, target
        p0 = (const float*)d_in[0]; t0 = (const float*)d_in[1];
        p1 = (const float*)d_in[2]; t1 = (const float*)d_in[3];
        p2 = (const float*)d_in[4]; t2 = (const float*)d_in[5];
    } else {
        // grouped: y_pred0..2, y_true0..2, target
        p0 = (const float*)d_in[0]; p1 = (const float*)d_in[1]; p2 = (const float*)d_in[2];
        t0 = (const float*)d_in[3]; t1 = (const float*)d_in[4]; t2 = (const float*)d_in[5];
    }
    const int B = in_sizes[6] / 100;   // target is (B, 20, 5)

    KParams kp;
    kp.target = (const float*)d_in[6];
    kp.out    = (float*)d_out;

    const int grids[3] = {13, 26, 52};
    const float aw[3][3] = {{116.f, 156.f, 373.f}, {30.f, 62.f, 59.f}, {10.f, 16.f, 33.f}};
    const float ah[3][3] = {{90.f, 198.f, 326.f},  {61.f, 45.f, 119.f}, {13.f, 30.f, 23.f}};
    const float* preds[3] = {p0, p1, p2};
    const float* trues[3] = {t0, t1, t2};

    int total = 0;
    for (int l = 0; l < 3; l++) {
        LayerParams& L = kp.L[l];
        L.pred = preds[l];
        L.ytr  = trues[l];
        L.ncells = B * 3 * grids[l] * grids[l];
        L.nblocks = (L.ncells + SLAB - 1) / SLAB;
        fill_anchors(L, aw[l], ah[l]);
        total += L.nblocks;
    }
    kp.totalBlocks = total;

    yolo_fused_kernel<<<total, TPB>>>(kp);
}

// round 11
// speedup vs baseline: 1.2882x; 1.2882x over previous
#include <cuda_runtime.h>
#include <cuda_bf16.h>

#define TPB  128
#define SLAB 128

__device__ double g_acc = 0.0;
__device__ unsigned int g_done = 0;

struct LayerParams {
    const float* pred;
    const float* ytr;
    int nblocks;
    int ncells;
    float s_aw[3], s_ah[3], i_aw[3], i_ah[3];
};

struct KParams {
    LayerParams L[3];
    const float* target;
    float* out;
    int totalBlocks;
};

// All 85 y_true values per cell stored as bf16 at smH[cell*86 + 1 + ch].
// Row stride 86 halves = 43 words (gcd(43,32)=1 -> conflict-free);
// +1 offset makes class pairs (ch=5+2m,6+2m) start at even half -> aligned bf16x2.
__shared__ __nv_bfloat16 smH[SLAB * 86];
__shared__ float         ws[4];

template<int G>
__device__ __forceinline__ float cell_loss(const float* __restrict__ pred,
                                           const float* __restrict__ target,
                                           int idx, const LayerParams& L)
{
    constexpr int cs = G * G;
    constexpr float invG = 1.f / (float)G;
    const int x = idx % G;
    const int y = (idx / G) % G;
    const int a = (idx / cs) % 3;
    const int b = idx / (3 * cs);

    const float* __restrict__ p = pred + ((size_t)(b * 255 + a * 85) * G + y) * G + x;
    const __nv_bfloat16* tR = smH + threadIdx.x * 86 + 1;

    const float s_aw = L.s_aw[a], s_ah = L.s_ah[a];
    const float i_aw = L.i_aw[a], i_ah = L.i_ah[a];

    const float r0 = p[0];
    const float r1 = p[cs];
    const float r2 = p[2 * cs];
    const float r3 = p[3 * cs];
    const float r4 = p[4 * cs];
    const float t0 = __bfloat162float(tR[0]);
    const float t1 = __bfloat162float(tR[1]);
    const float t2 = __bfloat162float(tR[2]);
    const float t3 = __bfloat162float(tR[3]);
    const float om = __bfloat162float(tR[4]);

    const float gx = (float)x, gy = (float)y;
    float loss = 0.f;

    // bce(sigmoid(r), t) = softplus(-r) + (1-t)*r
    const float e0 = __expf(-r0), e1 = __expf(-r1), e4 = __expf(-r4);
    const float sp0 = __logf(1.f + e0);
    const float sp1 = __logf(1.f + e1);
    const float sp4 = __logf(1.f + e4);

    // ---- xy loss ---- (ref: true_xy = y_true[...,0:2]*[h,w] - grid_xy)
    const float truex = t0 * (float)G - gx;
    const float truey = t1 * (float)G - gy;
    const float bce_x = sp0 + (1.f - truex) * r0;
    const float bce_y = sp1 + (1.f - truey) * r1;
    const float ls = 2.f - t2 * t3;
    loss += om * ls * (bce_x + bce_y);

    // ---- wh loss ----
    float twh = __logf(t2 * i_aw);
    float thh = __logf(t3 * i_ah);
    if (!(om > 0.f)) { twh = 0.f; thh = 0.f; }
    const float dw = r2 - twh, dh = r3 - thh;
    loss += om * ls * 0.5f * (dw * dw + dh * dh);

    // ---- predicted box for IoU ----
    const float sx = __fdividef(1.f, 1.f + e0);
    const float sy = __fdividef(1.f, 1.f + e1);
    const float bx = (sx + gx) * invG;
    const float by = (sy + gy) * invG;
    const float bw = __expf(r2) * s_aw;
    const float bh = __expf(r3) * s_ah;
    const float b1minx = bx - 0.5f * bw, b1maxx = bx + 0.5f * bw;
    const float b1miny = by - 0.5f * bh, b1maxy = by + 0.5f * bh;
    const float a1 = bw * bh;

    // best_iou < 0.5 <=> for all n: 3*inter < a1 + a2   (division-free; L1-broadcast)
    bool neg = true;
    const float* __restrict__ tg = target + b * 100;
    #pragma unroll 4
    for (int n = 0; n < 20; n++) {
        const float tx = tg[n * 5 + 0];
        const float ty = tg[n * 5 + 1];
        const float tw = tg[n * 5 + 2];
        const float th = tg[n * 5 + 3];
        const float hw = 0.5f * tw, hh = 0.5f * th;
        float iw = fminf(b1maxx, tx + hw) - fmaxf(b1minx, tx - hw);
        float ih = fminf(b1maxy, ty + hh) - fmaxf(b1miny, ty - hh);
        iw = fmaxf(iw, 0.f);
        ih = fmaxf(ih, 0.f);
        const float inter = iw * ih;
        neg = neg && (3.f * inter < fmaf(tw, th, a1));
    }
    const float negf = neg ? 1.f : 0.f;

    // ---- conf loss ----
    const float conf_bce = sp4 + (1.f - om) * r4;
    loss += (om + (1.f - om) * negf) * conf_bce;

    // ---- class loss: 8 groups of 10; QUAD product chains (depth ~3) and a
    //      single log per group: log(pa*pb*pc*pd). Max product 245^10 ~ 8e23,
    //      safely inside fp32 range. ----
    float cls = 0.f;
    #pragma unroll
    for (int g = 0; g < 8; g++) {
        float r[10];
        #pragma unroll
        for (int j = 0; j < 10; j++) r[j] = p[(size_t)(5 + g * 10 + j) * cs];

        float pa = 1.f, pb = 1.f, pc = 1.f, pd = 1.f;
        float lin = 0.f;
        #pragma unroll
        for (int j = 0; j < 8; j += 4) {
            pa = fmaf(pa, __expf(-r[j]),     pa);
            pb = fmaf(pb, __expf(-r[j + 1]), pb);
            pc = fmaf(pc, __expf(-r[j + 2]), pc);
            pd = fmaf(pd, __expf(-r[j + 3]), pd);
        }
        pa = fmaf(pa, __expf(-r[8]), pa);
        pb = fmaf(pb, __expf(-r[9]), pb);

        #pragma unroll
        for (int j = 0; j < 10; j += 2) {
            const __nv_bfloat162 tp =
                *reinterpret_cast<const __nv_bfloat162*>(tR + 5 + g * 10 + j);
            lin = fmaf(1.f - __low2float(tp),  r[j],     lin);
            lin = fmaf(1.f - __high2float(tp), r[j + 1], lin);
        }
        cls += __logf((pa * pb) * (pc * pd)) + lin;
    }
    loss += om * cls;
    return loss;
}

__global__ __launch_bounds__(TPB, 8)
void yolo_fused_kernel(KParams kp)
{
    int lb = blockIdx.x;
    int layer = 0;
    if (lb >= kp.L[0].nblocks) {
        lb -= kp.L[0].nblocks; layer = 1;
        if (lb >= kp.L[1].nblocks) { lb -= kp.L[1].nblocks; layer = 2; }
    }
    const LayerParams& L = kp.L[layer];
    const int cellBase = lb * SLAB;
    const int ncells = min(SLAB, L.ncells - cellBase);   // multiple of 32

    const int lane = threadIdx.x & 31;
    const int wid  = threadIdx.x >> 5;

    // ---- per-warp staging: 8 groups of 4 cells (= exactly 85 float4s each).
    //      All index math hoisted: per-slot offsets are group-invariant. ----
    {
        const int wCellBase = wid * 32;
        if (wCellBase < ncells) {
            const float* __restrict__ src = L.ytr + (size_t)(cellBase + wCellBase) * 85;
            const float4* __restrict__ s4 = (const float4*)src;

            // precompute (valid, half-offsets) for the 3 float4 slots of this lane
            int off[3][4];
            bool val[3];
            #pragma unroll
            for (int m = 0; m < 3; m++) {
                const int j = lane + 32 * m;          // float4 index within group
                val[m] = (j < 85);
                const int lf = 4 * j;                 // float index within group (4 cells)
                const int c  = lf / 85;               // cell-in-group
                const int ch = lf - 85 * c;           // channel
                #pragma unroll
                for (int k = 0; k < 4; k++) {
                    const int cch = ch + k;
                    const int cr  = (cch >= 85) ? 1 : 0;
                    off[m][k] = (c + cr) * 86 + 1 + (cch - 85 * cr);
                }
            }

            #pragma unroll
            for (int g = 0; g < 8; g++) {
                const float4* __restrict__ gs = s4 + 85 * g;
                __nv_bfloat16* dst = smH + (wCellBase + 4 * g) * 86;
                #pragma unroll
                for (int m = 0; m < 3; m++) {
                    if (val[m]) {
                        const float4 v = gs[lane + 32 * m];
                        dst[off[m][0]] = __float2bfloat16_rn(v.x);
                        dst[off[m][1]] = __float2bfloat16_rn(v.y);
                        dst[off[m][2]] = __float2bfloat16_rn(v.z);
                        dst[off[m][3]] = __float2bfloat16_rn(v.w);
                    }
                }
            }
        }
        __syncwarp();
    }

    float loss = 0.f;
    if (threadIdx.x < ncells) {
        const int idx = cellBase + threadIdx.x;
        if (layer == 0)      loss = cell_loss<13>(L.pred, kp.target, idx, L);
        else if (layer == 1) loss = cell_loss<26>(L.pred, kp.target, idx, L);
        else                 loss = cell_loss<52>(L.pred, kp.target, idx, L);
    }

    // ---- block reduction ----
    const unsigned m = 0xFFFFFFFFu;
    #pragma unroll
    for (int o = 16; o > 0; o >>= 1) loss += __shfl_down_sync(m, loss, o);
    if (lane == 0) ws[wid] = loss;
    __syncthreads();
    if (threadIdx.x == 0) {
        const float bs = ws[0] + ws[1] + ws[2] + ws[3];
        atomicAdd(&g_acc, (double)bs);
        __threadfence();
        const unsigned done = atomicAdd(&g_done, 1u);
        if (done == (unsigned)(kp.totalBlocks - 1)) {
            __threadfence();
            kp.out[0] = (float)g_acc;
            g_acc = 0.0;       // reset for next graph replay
            g_done = 0;
        }
    }
}

static void fill_anchors(LayerParams& L, const float* aw, const float* ah)
{
    for (int a = 0; a < 3; a++) {
        L.s_aw[a] = aw[a] / 416.f;
        L.s_ah[a] = ah[a] / 416.f;
        L.i_aw[a] = 416.f / aw[a];
        L.i_ah[a] = 416.f / ah[a];
    }
}

extern "C" void kernel_launch(void* const* d_in, const int* in_sizes, int n_in,
                              void* d_out, int out_size)
{
    const float *p0, *p1, *p2, *t0, *t1, *t2;
    if (in_sizes[1] == in_sizes[0]) {
        // interleaved: y_pred0, y_true0, y_pred1, y_true1, y_pred2, y_true2, target
        p0 = (const float*)d_in[0]; t0 = (const float*)d_in[1];
        p1 = (const float*)d_in[2]; t1 = (const float*)d_in[3];
        p2 = (const float*)d_in[4]; t2 = (const float*)d_in[5];
    } else {
        // grouped: y_pred0..2, y_true0..2, target
        p0 = (const float*)d_in[0]; p1 = (const float*)d_in[1]; p2 = (const float*)d_in[2];
        t0 = (const float*)d_in[3]; t1 = (const float*)d_in[4]; t2 = (const float*)d_in[5];
    }
    const int B = in_sizes[6] / 100;   // target is (B, 20, 5)

    KParams kp;
    kp.target = (const float*)d_in[6];
    kp.out    = (float*)d_out;

    const int grids[3] = {13, 26, 52};
    const float aw[3][3] = {{116.f, 156.f, 373.f}, {30.f, 62.f, 59.f}, {10.f, 16.f, 33.f}};
    const float ah[3][3] = {{90.f, 198.f, 326.f},  {61.f, 45.f, 119.f}, {13.f, 30.f, 23.f}};
    const float* preds[3] = {p0, p1, p2};
    const float* trues[3] = {t0, t1, t2};

    int total = 0;
    for (int l = 0; l < 3; l++) {
        LayerParams& L = kp.L[l];
        L.pred = preds[l];
        L.ytr  = trues[l];
        L.ncells = B * 3 * grids[l] * grids[l];
        L.nblocks = (L.ncells + SLAB - 1) / SLAB;
        fill_anchors(L, aw[l], ah[l]);
        total += L.nblocks;
    }
    kp.totalBlocks = total;

    yolo_fused_kernel<<<total, TPB>>>(kp);
}